// round 6
// baseline (speedup 1.0000x reference)
#include <cuda_runtime.h>
#include <cstdint>

#define N_NODES 50000
#define N_EDGES 800000
#define F_X 128
#define F_E 128
#define HIDDEN 512
#define F_OUT 128

// ---------------- scratch (static device globals; no runtime alloc) --------
__device__ float    g_agg[(size_t)N_NODES * F_E];              // 25.6 MB
__device__ uint32_t g_W1t[(size_t)HIDDEN * (F_E + F_X)];       // W1^T tf32 [512][256]
__device__ uint32_t g_W2t[(size_t)F_OUT * HIDDEN];             // W2^T tf32 [128][512]

__device__ __forceinline__ uint32_t f2tf32(float f) {
    uint32_t r; asm("cvt.rna.tf32.f32 %0, %1;" : "=r"(r) : "f"(f)); return r;
}

// ---------------------------------------------------------------------------
__global__ void zero_agg_kernel() {
    int i = blockIdx.x * blockDim.x + threadIdx.x;
    const int n4 = N_NODES * F_E / 4;
    float4* p = reinterpret_cast<float4*>(g_agg);
    if (i < n4) p[i] = make_float4(0.f, 0.f, 0.f, 0.f);
}

// ---------------------------------------------------------------------------
__global__ void __launch_bounds__(256) scatter_edges_kernel(
    const float4* __restrict__ edge_attr, const int* __restrict__ receivers)
{
    int gt = blockIdx.x * blockDim.x + threadIdx.x;
    int edge = gt >> 5;
    int lane = gt & 31;
    if (edge >= N_EDGES) return;

    int r = __ldg(receivers + edge);
    float4 v = edge_attr[(size_t)edge * 32 + lane];
    float* dst = g_agg + (size_t)r * F_E + lane * 4;
    asm volatile("red.global.add.v4.f32 [%0], {%1,%2,%3,%4};"
                 :: "l"(dst), "f"(v.x), "f"(v.y), "f"(v.z), "f"(v.w)
                 : "memory");
}

// ---------------------------------------------------------------------------
// W [K][N] row-major -> Wt [N][K] (tf32 bits, K contiguous)
// ---------------------------------------------------------------------------
__global__ void transpose_tf32_kernel(const float* __restrict__ W,
                                      uint32_t* __restrict__ Wt, int K, int N)
{
    int idx = blockIdx.x * blockDim.x + threadIdx.x;
    if (idx >= K * N) return;
    int n = idx / K;
    int k = idx - n * K;
    Wt[idx] = f2tf32(W[(size_t)k * N + n]);
}

// ---------------------------------------------------------------------------
// Fused MLP: out[128xB,128] = (ReLU([agg|nodes] @ W1 + b1)) @ W2 + b2
// per CTA: BM=128 rows, loop 4 hidden chunks of 128; h chunk lives in SMEM.
// 512 threads = 16 warps (4m x 4n), warp tile 32x32 = 2x4 m16n8k8.
// Dynamic SMEM: As [128][20] | Bs [128][20] | Hs [128][132] (tf32 bits)
// ---------------------------------------------------------------------------
#define SM_AS   0
#define SM_BS   (128 * 20)
#define SM_HS   (2 * 128 * 20)
#define SMEM_WORDS (2 * 128 * 20 + 128 * 132)

__global__ void __launch_bounds__(512)
fused_mlp_kernel(const float* __restrict__ nodes,
                 const uint32_t* __restrict__ W1t,
                 const float* __restrict__ b1,
                 const uint32_t* __restrict__ W2t,
                 const float* __restrict__ b2,
                 float* __restrict__ out)
{
    constexpr int M = N_NODES;
    extern __shared__ uint32_t smem[];
    uint32_t* As = smem + SM_AS;
    uint32_t* Bs = smem + SM_BS;
    uint32_t* Hs = smem + SM_HS;      // [128 m][132] tf32 bits

    const int tid  = threadIdx.x;
    const int lane = tid & 31;
    const int warp = tid >> 5;
    const int m0 = blockIdx.y * 128;
    const int warp_m = (warp >> 2) * 32;     // 0,32,64,96
    const int warp_n = (warp & 3) * 32;      // 0,32,64,96
    const int g  = lane >> 2;                // 0..7
    const int t4 = lane & 3;                 // 0..3

    // staging: 512 threads -> 1 float4 per thread per 128x16 slice
    const int srow = tid >> 2;               // 0..127
    const int sq   = tid & 3;                // 0..3

    float acc_out[2][4][4];
    #pragma unroll
    for (int mt = 0; mt < 2; ++mt)
        #pragma unroll
        for (int nt = 0; nt < 4; ++nt)
            #pragma unroll
            for (int i = 0; i < 4; ++i) acc_out[mt][nt][i] = 0.f;

    const int a_row_ok = (m0 + srow) < M;

    for (int hc = 0; hc < 4; ++hc) {
        // =============== Phase A: h_chunk = concat_A @ W1t[hc] ===============
        float acc_h[2][4][4];
        #pragma unroll
        for (int mt = 0; mt < 2; ++mt)
            #pragma unroll
            for (int nt = 0; nt < 4; ++nt)
                #pragma unroll
                for (int i = 0; i < 4; ++i) acc_h[mt][nt][i] = 0.f;

        for (int it = 0; it < 16; ++it) {
            const int k0 = it * 16;
            // issue global loads early (overlap prior tile's MMAs)
            const float* Abase = (k0 < F_E) ? g_agg : nodes;
            const int kofs = (k0 < F_E) ? k0 : (k0 - F_E);
            float4 va = make_float4(0.f, 0.f, 0.f, 0.f);
            if (a_row_ok)
                va = *reinterpret_cast<const float4*>(
                         Abase + (size_t)(m0 + srow) * 128 + kofs + sq * 4);
            uint4 vb = *reinterpret_cast<const uint4*>(
                           W1t + (size_t)(hc * 128 + srow) * 256 + k0 + sq * 4);

            __syncthreads();                  // prior compute done with As/Bs
            {
                uint4 ta;
                ta.x = f2tf32(va.x); ta.y = f2tf32(va.y);
                ta.z = f2tf32(va.z); ta.w = f2tf32(va.w);
                *reinterpret_cast<uint4*>(&As[srow * 20 + sq * 4]) = ta;
                *reinterpret_cast<uint4*>(&Bs[srow * 20 + sq * 4]) = vb;
            }
            __syncthreads();

            #pragma unroll
            for (int ks = 0; ks < 2; ++ks) {
                const int kb = ks * 8;
                uint32_t a[2][4], b[4][2];
                #pragma unroll
                for (int mt = 0; mt < 2; ++mt) {
                    int mb = warp_m + mt * 16;
                    a[mt][0] = As[(mb + g)     * 20 + kb + t4];
                    a[mt][1] = As[(mb + g + 8) * 20 + kb + t4];
                    a[mt][2] = As[(mb + g)     * 20 + kb + t4 + 4];
                    a[mt][3] = As[(mb + g + 8) * 20 + kb + t4 + 4];
                }
                #pragma unroll
                for (int nt = 0; nt < 4; ++nt) {
                    int nb = warp_n + nt * 8;
                    b[nt][0] = Bs[(nb + g) * 20 + kb + t4];
                    b[nt][1] = Bs[(nb + g) * 20 + kb + t4 + 4];
                }
                #pragma unroll
                for (int mt = 0; mt < 2; ++mt)
                    #pragma unroll
                    for (int nt = 0; nt < 4; ++nt)
                        asm volatile(
                            "mma.sync.aligned.m16n8k8.row.col.f32.tf32.tf32.f32 "
                            "{%0,%1,%2,%3}, {%4,%5,%6,%7}, {%8,%9}, {%0,%1,%2,%3};"
                            : "+f"(acc_h[mt][nt][0]), "+f"(acc_h[mt][nt][1]),
                              "+f"(acc_h[mt][nt][2]), "+f"(acc_h[mt][nt][3])
                            : "r"(a[mt][0]), "r"(a[mt][1]),
                              "r"(a[mt][2]), "r"(a[mt][3]),
                              "r"(b[nt][0]), "r"(b[nt][1]));
            }
        }

        // ---- bias + ReLU, write h chunk to SMEM as tf32 bits ----
        // (no sync needed: Hs disjoint from As/Bs, own-acc only)
        #pragma unroll
        for (int mt = 0; mt < 2; ++mt) {
            #pragma unroll
            for (int nt = 0; nt < 4; ++nt) {
                int c = warp_n + nt * 8 + t4 * 2;
                float2 bv = *reinterpret_cast<const float2*>(b1 + hc * 128 + c);
                #pragma unroll
                for (int hh = 0; hh < 2; ++hh) {
                    int r = warp_m + mt * 16 + g + hh * 8;
                    float ox = fmaxf(acc_h[mt][nt][hh * 2 + 0] + bv.x, 0.f);
                    float oy = fmaxf(acc_h[mt][nt][hh * 2 + 1] + bv.y, 0.f);
                    Hs[r * 132 + c]     = f2tf32(ox);
                    Hs[r * 132 + c + 1] = f2tf32(oy);
                }
            }
        }

        // =============== Phase B: acc_out += h_chunk @ W2t[:,hc] =============
        for (int it = 0; it < 8; ++it) {
            const int k0 = it * 16;
            uint4 vb = *reinterpret_cast<const uint4*>(
                           W2t + (size_t)srow * HIDDEN + hc * 128 + k0 + sq * 4);

            __syncthreads();   // Hs writes visible; prior compute done with Bs
            *reinterpret_cast<uint4*>(&Bs[srow * 20 + sq * 4]) = vb;
            __syncthreads();

            #pragma unroll
            for (int ks = 0; ks < 2; ++ks) {
                const int kb = ks * 8;
                const int kh = k0 + kb;       // k offset into Hs
                uint32_t a[2][4], b[4][2];
                #pragma unroll
                for (int mt = 0; mt < 2; ++mt) {
                    int mb = warp_m + mt * 16;
                    a[mt][0] = Hs[(mb + g)     * 132 + kh + t4];
                    a[mt][1] = Hs[(mb + g + 8) * 132 + kh + t4];
                    a[mt][2] = Hs[(mb + g)     * 132 + kh + t4 + 4];
                    a[mt][3] = Hs[(mb + g + 8) * 132 + kh + t4 + 4];
                }
                #pragma unroll
                for (int nt = 0; nt < 4; ++nt) {
                    int nb = warp_n + nt * 8;
                    b[nt][0] = Bs[(nb + g) * 20 + kb + t4];
                    b[nt][1] = Bs[(nb + g) * 20 + kb + t4 + 4];
                }
                #pragma unroll
                for (int mt = 0; mt < 2; ++mt)
                    #pragma unroll
                    for (int nt = 0; nt < 4; ++nt)
                        asm volatile(
                            "mma.sync.aligned.m16n8k8.row.col.f32.tf32.tf32.f32 "
                            "{%0,%1,%2,%3}, {%4,%5,%6,%7}, {%8,%9}, {%0,%1,%2,%3};"
                            : "+f"(acc_out[mt][nt][0]), "+f"(acc_out[mt][nt][1]),
                              "+f"(acc_out[mt][nt][2]), "+f"(acc_out[mt][nt][3])
                            : "r"(a[mt][0]), "r"(a[mt][1]),
                              "r"(a[mt][2]), "r"(a[mt][3]),
                              "r"(b[nt][0]), "r"(b[nt][1]));
            }
        }
        __syncthreads();   // all phase-B reads of Hs done before next chunk
    }

    // ---- epilogue: bias2, coalesced-ish float2 stores ----
    #pragma unroll
    for (int mt = 0; mt < 2; ++mt) {
        #pragma unroll
        for (int nt = 0; nt < 4; ++nt) {
            int gc = warp_n + nt * 8 + t4 * 2;
            float2 bv = *reinterpret_cast<const float2*>(b2 + gc);
            #pragma unroll
            for (int hh = 0; hh < 2; ++hh) {
                int gr = m0 + warp_m + mt * 16 + g + hh * 8;
                if (gr >= N_NODES) continue;
                float2 o;
                o.x = acc_out[mt][nt][hh * 2 + 0] + bv.x;
                o.y = acc_out[mt][nt][hh * 2 + 1] + bv.y;
                *reinterpret_cast<float2*>(out + (size_t)gr * F_OUT + gc) = o;
            }
        }
    }
}

// ---------------------------------------------------------------------------
// launch: zero -> scatter -> transpose W1/W2 -> fused MLP
// Inputs: nodes, edge_attr, senders, receivers, W1, b1, W2, b2
// ---------------------------------------------------------------------------
extern "C" void kernel_launch(void* const* d_in, const int* in_sizes, int n_in,
                              void* d_out, int out_size)
{
    const float*  nodes     = (const float*)d_in[0];
    const float4* edge_attr = (const float4*)d_in[1];
    const int*    receivers = (const int*)d_in[3];
    const float*  W1        = (const float*)d_in[4];
    const float*  b1        = (const float*)d_in[5];
    const float*  W2        = (const float*)d_in[6];
    const float*  b2        = (const float*)d_in[7];
    float* out = (float*)d_out;

    uint32_t* w1t = nullptr; uint32_t* w2t = nullptr;
    cudaGetSymbolAddress((void**)&w1t, g_W1t);
    cudaGetSymbolAddress((void**)&w2t, g_W2t);

    static bool attr_set = false;
    if (!attr_set) {
        cudaFuncSetAttribute(fused_mlp_kernel,
                             cudaFuncAttributeMaxDynamicSharedMemorySize,
                             SMEM_WORDS * 4);
        attr_set = true;
    }

    zero_agg_kernel<<<(N_NODES * F_E / 4 + 255) / 256, 256>>>();

    {
        long long total = (long long)N_EDGES * 32;
        int blocks = (int)((total + 255) / 256);
        scatter_edges_kernel<<<blocks, 256>>>(edge_attr, receivers);
    }

    transpose_tf32_kernel<<<((F_E + F_X) * HIDDEN + 255) / 256, 256>>>(
        W1, w1t, F_E + F_X, HIDDEN);
    transpose_tf32_kernel<<<(HIDDEN * F_OUT + 255) / 256, 256>>>(
        W2, w2t, HIDDEN, F_OUT);

    {
        dim3 grid(1, (N_NODES + 127) / 128);   // 391 CTAs
        fused_mlp_kernel<<<grid, 512, SMEM_WORDS * 4>>>(
            nodes, w1t, b1, w2t, b2, out);
    }
}

// round 7
// speedup vs baseline: 1.1926x; 1.1926x over previous
#include <cuda_runtime.h>
#include <cstdint>

#define N_NODES 50000
#define N_EDGES 800000
#define F_X 128
#define F_E 128
#define HIDDEN 512
#define F_OUT 128

// ---------------- scratch (static device globals; no runtime alloc) --------
__device__ float    g_agg[(size_t)N_NODES * F_E];              // 25.6 MB fp32
__device__ uint32_t g_A[(size_t)N_NODES * (F_E + F_X)];        // 51.2 MB tf32 [50000][256]
__device__ uint32_t g_h[(size_t)N_NODES * HIDDEN];             // 102.4 MB tf32 bits
__device__ uint32_t g_W1t[(size_t)HIDDEN * (F_E + F_X)];       // W1^T tf32 [512][256]
__device__ uint32_t g_W2t[(size_t)F_OUT * HIDDEN];             // W2^T tf32 [128][512]

__device__ __forceinline__ uint32_t f2tf32(float f) {
    uint32_t r; asm("cvt.rna.tf32.f32 %0, %1;" : "=r"(r) : "f"(f)); return r;
}
__device__ __forceinline__ uint32_t smem_u32(const void* p) {
    uint32_t a;
    asm("{ .reg .u64 t; cvta.to.shared.u64 t, %1; cvt.u32.u64 %0, t; }"
        : "=r"(a) : "l"(p));
    return a;
}

// ---------------------------------------------------------------------------
__global__ void zero_agg_kernel() {
    int i = blockIdx.x * blockDim.x + threadIdx.x;
    const int n4 = N_NODES * F_E / 4;
    float4* p = reinterpret_cast<float4*>(g_agg);
    if (i < n4) p[i] = make_float4(0.f, 0.f, 0.f, 0.f);
}

// ---------------------------------------------------------------------------
__global__ void __launch_bounds__(256) scatter_edges_kernel(
    const float4* __restrict__ edge_attr, const int* __restrict__ receivers)
{
    int gt = blockIdx.x * blockDim.x + threadIdx.x;
    int edge = gt >> 5;
    int lane = gt & 31;
    if (edge >= N_EDGES) return;

    int r = __ldg(receivers + edge);
    float4 v = edge_attr[(size_t)edge * 32 + lane];
    float* dst = g_agg + (size_t)r * F_E + lane * 4;
    asm volatile("red.global.add.v4.f32 [%0], {%1,%2,%3,%4};"
                 :: "l"(dst), "f"(v.x), "f"(v.y), "f"(v.z), "f"(v.w)
                 : "memory");
}

// ---------------------------------------------------------------------------
// W [K][N] row-major -> Wt [N][K] (tf32 bits, K contiguous)
// ---------------------------------------------------------------------------
__global__ void transpose_tf32_kernel(const float* __restrict__ W,
                                      uint32_t* __restrict__ Wt, int K, int N)
{
    int idx = blockIdx.x * blockDim.x + threadIdx.x;
    if (idx >= K * N) return;
    int n = idx / K;
    int k = idx - n * K;
    Wt[idx] = f2tf32(W[(size_t)k * N + n]);
}

// ---------------------------------------------------------------------------
// g_A[row][0:128] = tf32(g_agg[row]);  g_A[row][128:256] = tf32(nodes[row])
// ---------------------------------------------------------------------------
__global__ void __launch_bounds__(256) concat_tf32_kernel(
    const float4* __restrict__ nodes)
{
    int i = blockIdx.x * blockDim.x + threadIdx.x;      // float4 index
    const int total = N_NODES * 64;                     // 64 float4 per row
    if (i >= total) return;
    int row = i >> 6, c4 = i & 63;
    float4 v = (c4 < 32)
        ? reinterpret_cast<const float4*>(g_agg)[(size_t)row * 32 + c4]
        : nodes[(size_t)row * 32 + (c4 - 32)];
    uint4 t;
    t.x = f2tf32(v.x); t.y = f2tf32(v.y); t.z = f2tf32(v.z); t.w = f2tf32(v.w);
    reinterpret_cast<uint4*>(g_A)[i] = t;
}

// ---------------------------------------------------------------------------
// cp.async 4-stage pipelined tf32 mma GEMM.
// BM=128, BN=128, BK=16; 256 threads = 8 warps (2m x 4n), warp 64x32.
// L1=true : A=g_A (K=256), B=W1t, out = g_h (tf32 bits) with bias+ReLU
// L1=false: A=g_h (K=512), B=W2t, out = Cout (fp32) with bias
// SMEM per stage: A 128x20 + B 128x20 words; 4 stages = 80 KB dynamic.
// ---------------------------------------------------------------------------
#define STAGE_WORDS (2 * 128 * 20)          // 5120

template <bool L1>
__global__ void __launch_bounds__(256)
gemm_pipe_kernel(const uint32_t* __restrict__ Aglob,
                 const uint32_t* __restrict__ Wt,
                 const float* __restrict__ bias,
                 float* __restrict__ Cout)
{
    constexpr int K = L1 ? (F_E + F_X) : HIDDEN;
    constexpr int N = L1 ? HIDDEN : F_OUT;
    constexpr int M = N_NODES;
    constexpr int NT = K / 16;

    extern __shared__ uint32_t smem[];
    const uint32_t sbase = smem_u32(smem);

    const int tid  = threadIdx.x;
    const int lane = tid & 31;
    const int warp = tid >> 5;
    const int m0 = blockIdx.y * 128;
    const int n0 = blockIdx.x * 128;
    const int warp_m = (warp >> 2) * 64;
    const int warp_n = (warp & 3) * 32;
    const int g  = lane >> 2;
    const int t4 = lane & 3;

    // staging coords: 2 chunks of 16B per operand per thread
    const int row0 = tid >> 2,        q0 = tid & 3;            // e = tid
    const int row1 = (tid + 256) >> 2, q1 = tid & 3;           // e = tid+256

    const int a_ok0 = (m0 + row0) < M ? 16 : 0;
    const int a_ok1 = (m0 + row1) < M ? 16 : 0;

    float acc[4][4][4];
    #pragma unroll
    for (int mt = 0; mt < 4; ++mt)
        #pragma unroll
        for (int nt = 0; nt < 4; ++nt)
            #pragma unroll
            for (int i = 0; i < 4; ++i) acc[mt][nt][i] = 0.f;

    // ---- issue one tile's cp.asyncs into a slot ----
    auto issue = [&](int tile, int slot) {
        const int k0 = tile * 16;
        uint32_t ab = sbase + (slot * STAGE_WORDS) * 4;
        uint32_t bb = ab + 2560 * 4;
        // A chunk 0
        asm volatile("cp.async.cg.shared.global [%0], [%1], 16, %2;"
            :: "r"(ab + (row0 * 20 + q0 * 4) * 4),
               "l"(Aglob + (size_t)(m0 + row0) * K + k0 + q0 * 4),
               "r"(a_ok0) : "memory");
        // A chunk 1
        asm volatile("cp.async.cg.shared.global [%0], [%1], 16, %2;"
            :: "r"(ab + (row1 * 20 + q1 * 4) * 4),
               "l"(Aglob + (size_t)(m0 + row1) * K + k0 + q1 * 4),
               "r"(a_ok1) : "memory");
        // B chunk 0
        asm volatile("cp.async.cg.shared.global [%0], [%1], 16;"
            :: "r"(bb + (row0 * 20 + q0 * 4) * 4),
               "l"(Wt + (size_t)(n0 + row0) * K + k0 + q0 * 4) : "memory");
        // B chunk 1
        asm volatile("cp.async.cg.shared.global [%0], [%1], 16;"
            :: "r"(bb + (row1 * 20 + q1 * 4) * 4),
               "l"(Wt + (size_t)(n0 + row1) * K + k0 + q1 * 4) : "memory");
    };

    // ---- prologue: stages 0..2 ----
    issue(0, 0); asm volatile("cp.async.commit_group;" ::: "memory");
    issue(1, 1); asm volatile("cp.async.commit_group;" ::: "memory");
    issue(2, 2); asm volatile("cp.async.commit_group;" ::: "memory");

    for (int it = 0; it < NT; ++it) {
        asm volatile("cp.async.wait_group 2;" ::: "memory");
        __syncthreads();

        const uint32_t* As = smem + (it & 3) * STAGE_WORDS;
        const uint32_t* Bs = As + 2560;

        #pragma unroll
        for (int ks = 0; ks < 2; ++ks) {
            const int kb = ks * 8;
            uint32_t a[4][4], b[4][2];
            #pragma unroll
            for (int mt = 0; mt < 4; ++mt) {
                int mb = warp_m + mt * 16;
                a[mt][0] = As[(mb + g)     * 20 + kb + t4];
                a[mt][1] = As[(mb + g + 8) * 20 + kb + t4];
                a[mt][2] = As[(mb + g)     * 20 + kb + t4 + 4];
                a[mt][3] = As[(mb + g + 8) * 20 + kb + t4 + 4];
            }
            #pragma unroll
            for (int nt = 0; nt < 4; ++nt) {
                int nb = warp_n + nt * 8;
                b[nt][0] = Bs[(nb + g) * 20 + kb + t4];
                b[nt][1] = Bs[(nb + g) * 20 + kb + t4 + 4];
            }
            #pragma unroll
            for (int mt = 0; mt < 4; ++mt)
                #pragma unroll
                for (int nt = 0; nt < 4; ++nt)
                    asm volatile(
                        "mma.sync.aligned.m16n8k8.row.col.f32.tf32.tf32.f32 "
                        "{%0,%1,%2,%3}, {%4,%5,%6,%7}, {%8,%9}, {%0,%1,%2,%3};"
                        : "+f"(acc[mt][nt][0]), "+f"(acc[mt][nt][1]),
                          "+f"(acc[mt][nt][2]), "+f"(acc[mt][nt][3])
                        : "r"(a[mt][0]), "r"(a[mt][1]),
                          "r"(a[mt][2]), "r"(a[mt][3]),
                          "r"(b[nt][0]), "r"(b[nt][1]));
        }
        __syncthreads();

        if (it + 3 < NT) issue(it + 3, (it + 3) & 3);
        asm volatile("cp.async.commit_group;" ::: "memory");   // always: keep count exact
    }

    // ---- epilogue ----
    #pragma unroll
    for (int mt = 0; mt < 4; ++mt) {
        #pragma unroll
        for (int nt = 0; nt < 4; ++nt) {
            int gc = n0 + warp_n + nt * 8 + t4 * 2;
            float2 bv = *reinterpret_cast<const float2*>(bias + gc);
            #pragma unroll
            for (int hh = 0; hh < 2; ++hh) {
                int gr = m0 + warp_m + mt * 16 + g + hh * 8;
                if (gr >= M) continue;
                float ox = acc[mt][nt][hh * 2 + 0] + bv.x;
                float oy = acc[mt][nt][hh * 2 + 1] + bv.y;
                if (L1) {
                    uint2 t;
                    t.x = f2tf32(fmaxf(ox, 0.f));
                    t.y = f2tf32(fmaxf(oy, 0.f));
                    *reinterpret_cast<uint2*>(g_h + (size_t)gr * N + gc) = t;
                } else {
                    float2 o = make_float2(ox, oy);
                    *reinterpret_cast<float2*>(Cout + (size_t)gr * N + gc) = o;
                }
            }
        }
    }
}

// ---------------------------------------------------------------------------
// launch: zero -> scatter -> transposes -> concat -> gemm1 -> gemm2
// Inputs: nodes, edge_attr, senders, receivers, W1, b1, W2, b2
// ---------------------------------------------------------------------------
extern "C" void kernel_launch(void* const* d_in, const int* in_sizes, int n_in,
                              void* d_out, int out_size)
{
    const float*  nodes     = (const float*)d_in[0];
    const float4* edge_attr = (const float4*)d_in[1];
    const int*    receivers = (const int*)d_in[3];
    const float*  W1        = (const float*)d_in[4];
    const float*  b1        = (const float*)d_in[5];
    const float*  W2        = (const float*)d_in[6];
    const float*  b2        = (const float*)d_in[7];
    float* out = (float*)d_out;

    uint32_t *w1t = nullptr, *w2t = nullptr, *gA = nullptr, *gh = nullptr;
    cudaGetSymbolAddress((void**)&w1t, g_W1t);
    cudaGetSymbolAddress((void**)&w2t, g_W2t);
    cudaGetSymbolAddress((void**)&gA,  g_A);
    cudaGetSymbolAddress((void**)&gh,  g_h);

    static bool attr_set = false;
    if (!attr_set) {
        cudaFuncSetAttribute(gemm_pipe_kernel<true>,
                             cudaFuncAttributeMaxDynamicSharedMemorySize,
                             4 * STAGE_WORDS * 4);
        cudaFuncSetAttribute(gemm_pipe_kernel<false>,
                             cudaFuncAttributeMaxDynamicSharedMemorySize,
                             4 * STAGE_WORDS * 4);
        attr_set = true;
    }

    zero_agg_kernel<<<(N_NODES * F_E / 4 + 255) / 256, 256>>>();

    {
        long long total = (long long)N_EDGES * 32;
        int blocks = (int)((total + 255) / 256);
        scatter_edges_kernel<<<blocks, 256>>>(edge_attr, receivers);
    }

    transpose_tf32_kernel<<<((F_E + F_X) * HIDDEN + 255) / 256, 256>>>(
        W1, w1t, F_E + F_X, HIDDEN);
    transpose_tf32_kernel<<<(HIDDEN * F_OUT + 255) / 256, 256>>>(
        W2, w2t, HIDDEN, F_OUT);

    concat_tf32_kernel<<<(N_NODES * 64 + 255) / 256, 256>>>(
        (const float4*)nodes);

    {
        dim3 grid(HIDDEN / 128, (N_NODES + 127) / 128);   // (4, 391)
        gemm_pipe_kernel<true><<<grid, 256, 4 * STAGE_WORDS * 4>>>(
            gA, w1t, b1, nullptr);
    }
    {
        dim3 grid(F_OUT / 128, (N_NODES + 127) / 128);    // (1, 391)
        gemm_pipe_kernel<false><<<grid, 256, 4 * STAGE_WORDS * 4>>>(
            gh, w2t, b2, out);
    }
}